// round 1
// baseline (speedup 1.0000x reference)
#include <cuda_runtime.h>
#include <math.h>

// Problem constants
constexpr int BATCH = 4;
constexpr int NSEQ  = 2048;
constexpr int CDIM  = 1024;
constexpr int NHEAD = 16;
constexpr int DHEAD = 64;
constexpr int MROWS = BATCH * NSEQ;        // 8192
constexpr int F3C   = 3 * CDIM;            // 3072

// Scratch (static device globals — allocation-free per harness rules)
__device__ float g_qkv[MROWS * F3C];                     // [B*N, 3C]
__device__ float g_q[BATCH * NHEAD * NSEQ * DHEAD];      // [B,H,N,D]
__device__ float g_k[BATCH * NHEAD * NSEQ * DHEAD];
__device__ float g_v[BATCH * NHEAD * NSEQ * DHEAD];
__device__ float g_attn[MROWS * CDIM];                   // [B,N,C] = [B,N,H,D]

// ---------------------------------------------------------------------------
// Generic C = A * B^T (+bias). A:[M,K] row-major, B:[Nout,K] row-major.
// Tiles: 64x64 output, K-step 16, 256 threads, 4x4 per-thread micro-tile.
// smem stored K-major (transposed) so compute reads are float4 / conflict-free.
// ---------------------------------------------------------------------------
template <bool HAS_BIAS>
__global__ __launch_bounds__(256)
void gemm_abt(const float* __restrict__ A, const float* __restrict__ B,
              const float* __restrict__ bias, float* __restrict__ C,
              int M, int Nout, int K)
{
    __shared__ __align__(16) float As[16][64];
    __shared__ __align__(16) float Bs[16][64];

    const int t  = threadIdx.x;
    const int tx = t & 15;
    const int ty = t >> 4;
    const int m0 = blockIdx.y * 64;
    const int n0 = blockIdx.x * 64;

    // loader mapping: each thread loads one float4 per tile per matrix
    const int lr = t >> 2;       // row within tile (0..63)
    const int lq = t & 3;        // float4 index within 16-wide K slice (0..3)

    const float* Aptr = A + (size_t)(m0 + lr) * K + lq * 4;
    const float* Bptr = B + (size_t)(n0 + lr) * K + lq * 4;

    float acc[4][4] = {};

    for (int k0 = 0; k0 < K; k0 += 16) {
        float4 av = *(const float4*)(Aptr + k0);
        float4 bv = *(const float4*)(Bptr + k0);
        As[lq * 4 + 0][lr] = av.x;
        As[lq * 4 + 1][lr] = av.y;
        As[lq * 4 + 2][lr] = av.z;
        As[lq * 4 + 3][lr] = av.w;
        Bs[lq * 4 + 0][lr] = bv.x;
        Bs[lq * 4 + 1][lr] = bv.y;
        Bs[lq * 4 + 2][lr] = bv.z;
        Bs[lq * 4 + 3][lr] = bv.w;
        __syncthreads();

#pragma unroll
        for (int kk = 0; kk < 16; ++kk) {
            float4 a4 = *(const float4*)&As[kk][ty * 4];
            float4 b4 = *(const float4*)&Bs[kk][tx * 4];
            float a[4] = {a4.x, a4.y, a4.z, a4.w};
            float b[4] = {b4.x, b4.y, b4.z, b4.w};
#pragma unroll
            for (int i = 0; i < 4; ++i)
#pragma unroll
                for (int j = 0; j < 4; ++j)
                    acc[i][j] += a[i] * b[j];
        }
        __syncthreads();
    }

#pragma unroll
    for (int i = 0; i < 4; ++i) {
        const int m = m0 + ty * 4 + i;
#pragma unroll
        for (int j = 0; j < 4; ++j) {
            const int n = n0 + tx * 4 + j;
            float v = acc[i][j];
            if (HAS_BIAS) v += bias[n];
            C[(size_t)m * Nout + n] = v;
        }
    }
}

// ---------------------------------------------------------------------------
// RoPE + transpose: qkv [B,N,3C] -> Q/K/V [B,H,N,D], rope on Q,K.
// rotate_half: for d<32 partner is d+32 with sign -, else d-32 with sign +.
// ---------------------------------------------------------------------------
__global__ __launch_bounds__(256)
void rope_split_kernel(const float* __restrict__ rope_cos,
                       const float* __restrict__ rope_sin)
{
    const int idx = blockIdx.x * 256 + threadIdx.x;   // over B*H*N*D
    const int d = idx & (DHEAD - 1);
    const int n = (idx >> 6) & (NSEQ - 1);
    const int h = (idx >> 17) & (NHEAD - 1);
    const int b = idx >> 21;

    const size_t base = ((size_t)b * NSEQ + n) * F3C;
    const int fq = h * DHEAD + d;
    const int dp = (d < 32) ? d + 32 : d - 32;
    const int fp = h * DHEAD + dp;
    const float sgn = (d < 32) ? -1.0f : 1.0f;

    const float cs = rope_cos[n * DHEAD + d];
    const float sn = rope_sin[n * DHEAD + d];

    const float qv = g_qkv[base + fq];
    const float qp = g_qkv[base + fp];
    const float kv = g_qkv[base + CDIM + fq];
    const float kp = g_qkv[base + CDIM + fp];
    const float vv = g_qkv[base + 2 * CDIM + fq];

    const size_t o = (((size_t)b * NHEAD + h) * NSEQ + n) * DHEAD + d;
    g_q[o] = qv * cs + sgn * qp * sn;
    g_k[o] = kv * cs + sgn * kp * sn;
    g_v[o] = vv;
}

// ---------------------------------------------------------------------------
// Flash attention: per (b, h, 64-row q tile). K-tile = 32. Streaming softmax.
// 256 threads = 16x16; thread owns 4 q-rows x (2 key-cols for S, 4 d-cols for O).
// smem: Q 64x68, K 32x68, V 32x68, P 64x36 = 44 KB.
// ---------------------------------------------------------------------------
constexpr int BQ = 64;
constexpr int BKT = 32;
constexpr int DP = DHEAD + 4;   // 68, padded to kill bank conflicts

__global__ __launch_bounds__(256)
void attn_kernel(float* __restrict__ Oout)
{
    __shared__ __align__(16) float Qs[BQ][DP];
    __shared__ __align__(16) float Ks[BKT][DP];
    __shared__ __align__(16) float Vs[BKT][DP];
    __shared__ float Ps[BQ][BKT + 4];

    const int qt = blockIdx.x;
    const int h  = blockIdx.y;
    const int b  = blockIdx.z;
    const int t  = threadIdx.x;
    const int tx = t & 15;
    const int ty = t >> 4;

    const float* Qb = g_q + (((size_t)b * NHEAD + h) * NSEQ + qt * BQ) * DHEAD;
    const float* Kb = g_k + (((size_t)b * NHEAD + h) * NSEQ) * DHEAD;
    const float* Vb = g_v + (((size_t)b * NHEAD + h) * NSEQ) * DHEAD;

    // load Q tile: 64*64 floats = 1024 float4, 4 per thread
#pragma unroll
    for (int i = t; i < BQ * DHEAD / 4; i += 256) {
        const int r = i >> 4, c4 = i & 15;
        *(float4*)&Qs[r][c4 * 4] = *(const float4*)(Qb + r * DHEAD + c4 * 4);
    }

    float m_i[4], l_i[4], o[4][4];
#pragma unroll
    for (int i = 0; i < 4; ++i) {
        m_i[i] = -INFINITY;
        l_i[i] = 0.0f;
#pragma unroll
        for (int j = 0; j < 4; ++j) o[i][j] = 0.0f;
    }
    __syncthreads();

    const float scale = 0.125f;   // D^-0.5

    for (int kt = 0; kt < NSEQ / BKT; ++kt) {
        // load K,V tiles: 512 float4 each, 2 per thread each
#pragma unroll
        for (int i = t; i < BKT * DHEAD / 4; i += 256) {
            const int r = i >> 4, c4 = i & 15;
            *(float4*)&Ks[r][c4 * 4] =
                *(const float4*)(Kb + (size_t)(kt * BKT + r) * DHEAD + c4 * 4);
            *(float4*)&Vs[r][c4 * 4] =
                *(const float4*)(Vb + (size_t)(kt * BKT + r) * DHEAD + c4 * 4);
        }
        __syncthreads();

        // S = Q * K^T : rows ty*4+i, cols tx*2+j
        float s[4][2] = {};
#pragma unroll
        for (int d4 = 0; d4 < 16; ++d4) {
            float4 k0 = *(const float4*)&Ks[tx * 2 + 0][d4 * 4];
            float4 k1 = *(const float4*)&Ks[tx * 2 + 1][d4 * 4];
#pragma unroll
            for (int i = 0; i < 4; ++i) {
                float4 q4 = *(const float4*)&Qs[ty * 4 + i][d4 * 4];
                s[i][0] += q4.x * k0.x + q4.y * k0.y + q4.z * k0.z + q4.w * k0.w;
                s[i][1] += q4.x * k1.x + q4.y * k1.y + q4.z * k1.z + q4.w * k1.w;
            }
        }

        // streaming softmax per row (16-lane row-groups within the warp)
#pragma unroll
        for (int i = 0; i < 4; ++i) {
            float s0 = s[i][0] * scale;
            float s1 = s[i][1] * scale;
            float mx = fmaxf(s0, s1);
#pragma unroll
            for (int off = 8; off > 0; off >>= 1)
                mx = fmaxf(mx, __shfl_xor_sync(0xffffffffu, mx, off));
            const float m_new = fmaxf(m_i[i], mx);
            const float p0 = __expf(s0 - m_new);
            const float p1 = __expf(s1 - m_new);
            const float corr = __expf(m_i[i] - m_new);
            float rs = p0 + p1;
#pragma unroll
            for (int off = 8; off > 0; off >>= 1)
                rs += __shfl_xor_sync(0xffffffffu, rs, off);
            l_i[i] = l_i[i] * corr + rs;
            m_i[i] = m_new;
#pragma unroll
            for (int j = 0; j < 4; ++j) o[i][j] *= corr;
            Ps[ty * 4 + i][tx * 2 + 0] = p0;
            Ps[ty * 4 + i][tx * 2 + 1] = p1;
        }
        __syncthreads();

        // O += P * V : rows ty*4+i, d-cols tx*4+j
#pragma unroll
        for (int kk = 0; kk < BKT; ++kk) {
            float4 v4 = *(const float4*)&Vs[kk][tx * 4];
#pragma unroll
            for (int i = 0; i < 4; ++i) {
                const float p = Ps[ty * 4 + i][kk];
                o[i][0] += p * v4.x;
                o[i][1] += p * v4.y;
                o[i][2] += p * v4.z;
                o[i][3] += p * v4.w;
            }
        }
        __syncthreads();
    }

    // epilogue: normalize and write to [B, N, H*D]
#pragma unroll
    for (int i = 0; i < 4; ++i) {
        const int n = qt * BQ + ty * 4 + i;
        const float inv = 1.0f / l_i[i];
#pragma unroll
        for (int j = 0; j < 4; ++j) {
            Oout[((size_t)b * NSEQ + n) * CDIM + h * DHEAD + tx * 4 + j] =
                o[i][j] * inv;
        }
    }
}

// ---------------------------------------------------------------------------
extern "C" void kernel_launch(void* const* d_in, const int* in_sizes, int n_in,
                              void* d_out, int out_size)
{
    const float* x        = (const float*)d_in[0];
    const float* rope_cos = (const float*)d_in[1];
    const float* rope_sin = (const float*)d_in[2];
    const float* w_qkv    = (const float*)d_in[3];
    const float* w_proj   = (const float*)d_in[4];
    const float* b_proj   = (const float*)d_in[5];
    float* out = (float*)d_out;

    float *qkv_p, *attn_p;
    cudaGetSymbolAddress((void**)&qkv_p, g_qkv);
    cudaGetSymbolAddress((void**)&attn_p, g_attn);

    // 1) QKV projection: [8192,1024] x [3072,1024]^T -> [8192,3072]
    {
        dim3 grid(F3C / 64, MROWS / 64);
        gemm_abt<false><<<grid, 256>>>(x, w_qkv, nullptr, qkv_p,
                                       MROWS, F3C, CDIM);
    }

    // 2) RoPE + split/transpose to [B,H,N,D]
    {
        const int total = BATCH * NHEAD * NSEQ * DHEAD;
        rope_split_kernel<<<total / 256, 256>>>(rope_cos, rope_sin);
    }

    // 3) Flash attention -> g_attn [B,N,C]
    {
        dim3 grid(NSEQ / BQ, NHEAD, BATCH);
        attn_kernel<<<grid, 256>>>(attn_p);
    }

    // 4) Output projection + bias: [8192,1024] x [1024,1024]^T + b
    {
        dim3 grid(CDIM / 64, MROWS / 64);
        gemm_abt<true><<<grid, 256>>>(attn_p, w_proj, b_proj, out,
                                      MROWS, CDIM, CDIM);
    }
}

// round 4
// speedup vs baseline: 4.0010x; 4.0010x over previous
#include <cuda_runtime.h>
#include <math.h>
#include <stdint.h>

// Problem constants
constexpr int BATCH = 4;
constexpr int NSEQ  = 2048;
constexpr int CDIM  = 1024;
constexpr int NHEAD = 16;
constexpr int DHEAD = 64;
constexpr int MROWS = BATCH * NSEQ;        // 8192
constexpr int F3C   = 3 * CDIM;            // 3072

// Scratch (static device globals — allocation-free per harness rules)
__device__ float g_qkv[MROWS * F3C];                     // [B*N, 3C]
__device__ float g_q[BATCH * NHEAD * NSEQ * DHEAD];      // [B,H,N,D]
__device__ float g_k[BATCH * NHEAD * NSEQ * DHEAD];
__device__ float g_v[BATCH * NHEAD * NSEQ * DHEAD];
__device__ float g_attn[MROWS * CDIM];                   // [B,N,C]

// ===========================================================================
// Helpers: tf32 convert + mma.sync (arch-agnostic PTX; works on target sm_103)
// ===========================================================================
__device__ __forceinline__ uint32_t f2tf32(float f) {
    uint32_t u;
    asm("cvt.rna.tf32.f32 %0, %1;" : "=r"(u) : "f"(f));
    return u;
}

// D(16x8,f32) += A(16x8,tf32) * B(8x8,tf32)
// Fragment layout (lane l, lg=l/4, lq=l%4):
//   a0=(lg,lq) a1=(lg+8,lq) a2=(lg,lq+4) a3=(lg+8,lq+4)
//   b0=(k=lq,n=lg) b1=(k=lq+4,n=lg)
//   c0=(lg,2lq) c1=(lg,2lq+1) c2=(lg+8,2lq) c3=(lg+8,2lq+1)
__device__ __forceinline__ void mma8(float* c, const uint32_t* a,
                                     uint32_t b0, uint32_t b1) {
    asm volatile(
        "mma.sync.aligned.m16n8k8.row.col.f32.tf32.tf32.f32 "
        "{%0,%1,%2,%3}, {%4,%5,%6,%7}, {%8,%9}, {%0,%1,%2,%3};\n"
        : "+f"(c[0]), "+f"(c[1]), "+f"(c[2]), "+f"(c[3])
        : "r"(a[0]), "r"(a[1]), "r"(a[2]), "r"(a[3]), "r"(b0), "r"(b1));
}

// ===========================================================================
// tf32 tensor GEMM: C = A * B^T (+bias).  A:[M,K], B:[Nout,K], row-major.
// CTA 128x128x32, 256 threads (8 warps), warp tile 32x64.
// SMEM row stride 36 u32 -> fragment loads hit banks 4*lg+lq (conflict-free).
// ===========================================================================
constexpr int BM = 128, BN = 128, BK = 32;
constexpr int ASTR = BK + 4;   // 36

template <bool HAS_BIAS>
__global__ __launch_bounds__(256)
void gemm_mma(const float* __restrict__ A, const float* __restrict__ B,
              const float* __restrict__ bias, float* __restrict__ C,
              int M, int Nout, int K)
{
    __shared__ uint32_t As[BM * ASTR];
    __shared__ uint32_t Bs[BN * ASTR];

    const int t   = threadIdx.x;
    const int wid = t >> 5;
    const int l   = t & 31;
    const int lg  = l >> 2;
    const int lq  = l & 3;
    const int wr  = wid & 3;       // m: 4 warps * 32 rows
    const int wc  = wid >> 2;      // n: 2 warps * 64 cols
    const int m0  = blockIdx.y * BM;
    const int n0  = blockIdx.x * BN;

    float acc[2][8][4];
#pragma unroll
    for (int mi = 0; mi < 2; ++mi)
#pragma unroll
        for (int j = 0; j < 8; ++j)
#pragma unroll
            for (int e = 0; e < 4; ++e) acc[mi][j][e] = 0.0f;

    for (int k0 = 0; k0 < K; k0 += BK) {
        // A tile 128x32 = 1024 uint4 slots; B tile same. 4 each per thread.
#pragma unroll
        for (int i = 0; i < 4; ++i) {
            const int idx = t + i * 256;
            const int r = idx >> 3, c4 = idx & 7;
            float4 va = *(const float4*)(A + (size_t)(m0 + r) * K + k0 + c4 * 4);
            float4 vb = *(const float4*)(B + (size_t)(n0 + r) * K + k0 + c4 * 4);
            uint4 ua = make_uint4(f2tf32(va.x), f2tf32(va.y),
                                  f2tf32(va.z), f2tf32(va.w));
            uint4 ub = make_uint4(f2tf32(vb.x), f2tf32(vb.y),
                                  f2tf32(vb.z), f2tf32(vb.w));
            *(uint4*)&As[r * ASTR + c4 * 4] = ua;
            *(uint4*)&Bs[r * ASTR + c4 * 4] = ub;
        }
        __syncthreads();

#pragma unroll
        for (int ks = 0; ks < 4; ++ks) {
            uint32_t af[2][4];
#pragma unroll
            for (int mi = 0; mi < 2; ++mi) {
                const int row = wr * 32 + mi * 16;
                af[mi][0] = As[(row + lg)     * ASTR + ks * 8 + lq];
                af[mi][1] = As[(row + lg + 8) * ASTR + ks * 8 + lq];
                af[mi][2] = As[(row + lg)     * ASTR + ks * 8 + lq + 4];
                af[mi][3] = As[(row + lg + 8) * ASTR + ks * 8 + lq + 4];
            }
#pragma unroll
            for (int j = 0; j < 8; ++j) {
                const int n = wc * 64 + j * 8 + lg;
                const uint32_t b0 = Bs[n * ASTR + ks * 8 + lq];
                const uint32_t b1 = Bs[n * ASTR + ks * 8 + lq + 4];
                mma8(acc[0][j], af[0], b0, b1);
                mma8(acc[1][j], af[1], b0, b1);
            }
        }
        __syncthreads();
    }

    // Epilogue: float2 stores (cols 2lq, 2lq+1)
#pragma unroll
    for (int mi = 0; mi < 2; ++mi) {
        const int r0 = m0 + wr * 32 + mi * 16 + lg;
#pragma unroll
        for (int j = 0; j < 8; ++j) {
            const int c = n0 + wc * 64 + j * 8 + 2 * lq;
            float2 v0 = make_float2(acc[mi][j][0], acc[mi][j][1]);
            float2 v1 = make_float2(acc[mi][j][2], acc[mi][j][3]);
            if (HAS_BIAS) {
                float2 bv = *(const float2*)(bias + c);
                v0.x += bv.x; v0.y += bv.y;
                v1.x += bv.x; v1.y += bv.y;
            }
            *(float2*)(C + (size_t)r0 * Nout + c) = v0;
            *(float2*)(C + (size_t)(r0 + 8) * Nout + c) = v1;
        }
    }
}

// ---------------------------------------------------------------------------
// RoPE + transpose: qkv [B,N,3C] -> Q/K/V [B,H,N,D], rope on Q,K.
// ---------------------------------------------------------------------------
__global__ __launch_bounds__(256)
void rope_split_kernel(const float* __restrict__ rope_cos,
                       const float* __restrict__ rope_sin)
{
    const int idx = blockIdx.x * 256 + threadIdx.x;
    const int d = idx & (DHEAD - 1);
    const int n = (idx >> 6) & (NSEQ - 1);
    const int h = (idx >> 17) & (NHEAD - 1);
    const int b = idx >> 21;

    const size_t base = ((size_t)b * NSEQ + n) * F3C;
    const int fq = h * DHEAD + d;
    const int dp = (d < 32) ? d + 32 : d - 32;
    const int fp = h * DHEAD + dp;
    const float sgn = (d < 32) ? -1.0f : 1.0f;

    const float cs = rope_cos[n * DHEAD + d];
    const float sn = rope_sin[n * DHEAD + d];

    const float qv = g_qkv[base + fq];
    const float qp = g_qkv[base + fp];
    const float kv = g_qkv[base + CDIM + fq];
    const float kp = g_qkv[base + CDIM + fp];
    const float vv = g_qkv[base + 2 * CDIM + fq];

    const size_t o = (((size_t)b * NHEAD + h) * NSEQ + n) * DHEAD + d;
    g_q[o] = qv * cs + sgn * qp * sn;
    g_k[o] = kv * cs + sgn * kp * sn;
    g_v[o] = vv;
}

// ===========================================================================
// Flash attention with tf32 mma.sync.
// CTA = (b, h, 64 q rows), 4 warps; warp owns 16 q rows.
// K-tile = 32 keys. Q a-frags preloaded (scaled). P staged in per-warp SMEM.
// Ks stride 68 u32 (banks 4lg+lq), Vs stride 72 (banks 8lq+lg), Ps stride 36.
// ===========================================================================
constexpr int ABQ = 64, ABK = 32;
constexpr int KSTR = 68, VSTR = 72, PSTR = 36;

__global__ __launch_bounds__(128)
void attn_mma(float* __restrict__ Oout)
{
    __shared__ uint32_t Ks[ABK * KSTR];
    __shared__ uint32_t Vs[ABK * VSTR];
    __shared__ uint32_t Ps[ABQ * PSTR];

    const int qt = blockIdx.x;
    const int h  = blockIdx.y;
    const int b  = blockIdx.z;
    const int t  = threadIdx.x;
    const int wid = t >> 5;
    const int l   = t & 31;
    const int lg  = l >> 2;
    const int lq  = l & 3;

    const float* Qb = g_q + (((size_t)b * NHEAD + h) * NSEQ + qt * ABQ + wid * 16) * DHEAD;
    const float* Kb = g_k + (((size_t)b * NHEAD + h) * NSEQ) * DHEAD;
    const float* Vb = g_v + (((size_t)b * NHEAD + h) * NSEQ) * DHEAD;

    // Preload Q a-fragments for all 8 k-steps, pre-scaled by D^-0.5 (exact pow2)
    const float scale = 0.125f;
    uint32_t qf[8][4];
#pragma unroll
    for (int ks = 0; ks < 8; ++ks) {
        const int col = ks * 8 + lq;
        qf[ks][0] = f2tf32(Qb[(size_t)lg * DHEAD + col] * scale);
        qf[ks][1] = f2tf32(Qb[(size_t)(lg + 8) * DHEAD + col] * scale);
        qf[ks][2] = f2tf32(Qb[(size_t)lg * DHEAD + col + 4] * scale);
        qf[ks][3] = f2tf32(Qb[(size_t)(lg + 8) * DHEAD + col + 4] * scale);
    }

    float m_i[2] = {-INFINITY, -INFINITY};
    float l_i[2] = {0.0f, 0.0f};
    float o[8][4];
#pragma unroll
    for (int j = 0; j < 8; ++j)
#pragma unroll
        for (int e = 0; e < 4; ++e) o[j][e] = 0.0f;

    for (int kt = 0; kt < NSEQ / ABK; ++kt) {
        __syncthreads();   // all warps done with previous Ks/Vs
        // load K,V tiles 32x64: 512 float4 each, 4 per thread each
#pragma unroll
        for (int i = 0; i < 4; ++i) {
            const int idx = t + i * 128;
            const int r = idx >> 4, c4 = idx & 15;
            float4 kv = *(const float4*)(Kb + (size_t)(kt * ABK + r) * DHEAD + c4 * 4);
            float4 vv = *(const float4*)(Vb + (size_t)(kt * ABK + r) * DHEAD + c4 * 4);
            uint4 uk = make_uint4(f2tf32(kv.x), f2tf32(kv.y),
                                  f2tf32(kv.z), f2tf32(kv.w));
            uint4 uv = make_uint4(f2tf32(vv.x), f2tf32(vv.y),
                                  f2tf32(vv.z), f2tf32(vv.w));
            *(uint4*)&Ks[r * KSTR + c4 * 4] = uk;
            *(uint4*)&Vs[r * VSTR + c4 * 4] = uv;
        }
        __syncthreads();

        // S = (Q*scale) * K^T : 4 n-frags (32 keys), 8 k-steps
        float s[4][4];
#pragma unroll
        for (int j = 0; j < 4; ++j)
#pragma unroll
            for (int e = 0; e < 4; ++e) s[j][e] = 0.0f;

#pragma unroll
        for (int ks = 0; ks < 8; ++ks) {
#pragma unroll
            for (int j = 0; j < 4; ++j) {
                const int key = j * 8 + lg;
                const uint32_t b0 = Ks[key * KSTR + ks * 8 + lq];
                const uint32_t b1 = Ks[key * KSTR + ks * 8 + lq + 4];
                mma8(s[j], qf[ks], b0, b1);
            }
        }

        // Streaming softmax: rows lg (regs 0,1) and lg+8 (regs 2,3);
        // row spans 4 lanes (lq=0..3) x 4 n-frags x 2 cols.
        float mx0 = -INFINITY, mx1 = -INFINITY;
#pragma unroll
        for (int j = 0; j < 4; ++j) {
            mx0 = fmaxf(mx0, fmaxf(s[j][0], s[j][1]));
            mx1 = fmaxf(mx1, fmaxf(s[j][2], s[j][3]));
        }
        mx0 = fmaxf(mx0, __shfl_xor_sync(0xffffffffu, mx0, 1));
        mx0 = fmaxf(mx0, __shfl_xor_sync(0xffffffffu, mx0, 2));
        mx1 = fmaxf(mx1, __shfl_xor_sync(0xffffffffu, mx1, 1));
        mx1 = fmaxf(mx1, __shfl_xor_sync(0xffffffffu, mx1, 2));

        const float mn0 = fmaxf(m_i[0], mx0);
        const float mn1 = fmaxf(m_i[1], mx1);
        const float c0 = __expf(m_i[0] - mn0);
        const float c1 = __expf(m_i[1] - mn1);
        m_i[0] = mn0; m_i[1] = mn1;

        float rs0 = 0.0f, rs1 = 0.0f;
#pragma unroll
        for (int j = 0; j < 4; ++j) {
            float p0 = __expf(s[j][0] - mn0);
            float p1 = __expf(s[j][1] - mn0);
            float p2 = __expf(s[j][2] - mn1);
            float p3 = __expf(s[j][3] - mn1);
            rs0 += p0 + p1;
            rs1 += p2 + p3;
            uint32_t* pr0 = &Ps[(wid * 16 + lg) * PSTR + j * 8 + 2 * lq];
            uint32_t* pr1 = &Ps[(wid * 16 + lg + 8) * PSTR + j * 8 + 2 * lq];
            pr0[0] = f2tf32(p0); pr0[1] = f2tf32(p1);
            pr1[0] = f2tf32(p2); pr1[1] = f2tf32(p3);
        }
        rs0 += __shfl_xor_sync(0xffffffffu, rs0, 1);
        rs0 += __shfl_xor_sync(0xffffffffu, rs0, 2);
        rs1 += __shfl_xor_sync(0xffffffffu, rs1, 1);
        rs1 += __shfl_xor_sync(0xffffffffu, rs1, 2);
        l_i[0] = l_i[0] * c0 + rs0;
        l_i[1] = l_i[1] * c1 + rs1;

#pragma unroll
        for (int j = 0; j < 8; ++j) {
            o[j][0] *= c0; o[j][1] *= c0;
            o[j][2] *= c1; o[j][3] *= c1;
        }

        __syncwarp();   // P stores visible to whole warp

        // O += P * V : 4 k-steps (32 keys), 8 n-frags (D=64)
#pragma unroll
        for (int ks = 0; ks < 4; ++ks) {
            uint32_t af[4];
            af[0] = Ps[(wid * 16 + lg)     * PSTR + ks * 8 + lq];
            af[1] = Ps[(wid * 16 + lg + 8) * PSTR + ks * 8 + lq];
            af[2] = Ps[(wid * 16 + lg)     * PSTR + ks * 8 + lq + 4];
            af[3] = Ps[(wid * 16 + lg + 8) * PSTR + ks * 8 + lq + 4];
#pragma unroll
            for (int j = 0; j < 8; ++j) {
                const uint32_t b0 = Vs[(ks * 8 + lq)     * VSTR + j * 8 + lg];
                const uint32_t b1 = Vs[(ks * 8 + lq + 4) * VSTR + j * 8 + lg];
                mma8(o[j], af, b0, b1);
            }
        }
        __syncwarp();   // PV reads done before next iter's P stores
    }

    // Epilogue: normalize, write [B,N,H*D]
    const float inv0 = 1.0f / l_i[0];
    const float inv1 = 1.0f / l_i[1];
    const int n0 = qt * ABQ + wid * 16 + lg;
#pragma unroll
    for (int j = 0; j < 8; ++j) {
        const int c = h * DHEAD + j * 8 + 2 * lq;
        *(float2*)(Oout + ((size_t)b * NSEQ + n0) * CDIM + c) =
            make_float2(o[j][0] * inv0, o[j][1] * inv0);
        *(float2*)(Oout + ((size_t)b * NSEQ + n0 + 8) * CDIM + c) =
            make_float2(o[j][2] * inv1, o[j][3] * inv1);
    }
}

// ---------------------------------------------------------------------------
extern "C" void kernel_launch(void* const* d_in, const int* in_sizes, int n_in,
                              void* d_out, int out_size)
{
    const float* x        = (const float*)d_in[0];
    const float* rope_cos = (const float*)d_in[1];
    const float* rope_sin = (const float*)d_in[2];
    const float* w_qkv    = (const float*)d_in[3];
    const float* w_proj   = (const float*)d_in[4];
    const float* b_proj   = (const float*)d_in[5];
    float* out = (float*)d_out;

    float *qkv_p, *attn_p;
    cudaGetSymbolAddress((void**)&qkv_p, g_qkv);
    cudaGetSymbolAddress((void**)&attn_p, g_attn);

    // 1) QKV projection (tf32 mma): [8192,1024] x [3072,1024]^T
    {
        dim3 grid(F3C / BN, MROWS / BM);
        gemm_mma<false><<<grid, 256>>>(x, w_qkv, nullptr, qkv_p,
                                       MROWS, F3C, CDIM);
    }

    // 2) RoPE + split/transpose to [B,H,N,D]
    {
        const int total = BATCH * NHEAD * NSEQ * DHEAD;
        rope_split_kernel<<<total / 256, 256>>>(rope_cos, rope_sin);
    }

    // 3) Flash attention (tf32 mma) -> g_attn [B,N,C]
    {
        dim3 grid(NSEQ / ABQ, NHEAD, BATCH);
        attn_mma<<<grid, 128>>>(attn_p);
    }

    // 4) Output projection + bias (tf32 mma)
    {
        dim3 grid(CDIM / BN, MROWS / BM);
        gemm_mma<true><<<grid, 256>>>(attn_p, w_proj, b_proj, out,
                                      MROWS, CDIM, CDIM);
    }
}